// round 4
// baseline (speedup 1.0000x reference)
#include <cuda_runtime.h>

#define BB 8
#define CC 192
#define CQ 32
#define NN 16384
#define TILE 64
#define NT (NN / TILE)   // 256 tiles per batch

typedef unsigned long long u64;

// ---------------- f32x2 packed-FMA helpers (sm_100+; SASS FFMA2) ----------------
__device__ __forceinline__ u64 pack2(float x, float y) {
    u64 r; asm("mov.b64 %0, {%1, %2};" : "=l"(r) : "f"(x), "f"(y)); return r;
}
__device__ __forceinline__ u64 pack2s(float x) { return pack2(x, x); }
__device__ __forceinline__ void fma2(u64& d, u64 a, u64 b) {
    asm("fma.rn.f32x2 %0, %1, %2, %0;" : "+l"(d) : "l"(a), "l"(b));
}
__device__ __forceinline__ float2 unpk2(u64 v) {
    float2 f; asm("mov.b64 {%0, %1}, %2;" : "=f"(f.x), "=f"(f.y) : "l"(v)); return f;
}

// ---------------- scratch (static device globals; no allocations) ----------------
__device__ float g_Qn[(size_t)BB * NN * CQ];            // [b][n][r]
__device__ float g_Kn[(size_t)BB * CQ * NN];            // [b][r][n]
__device__ float g_MatPart[(size_t)BB * NT * CQ * CC];
__device__ float g_VsumPart[(size_t)BB * NT * CC];
__device__ float g_Mat[BB * CQ * CC];
__device__ float g_Vsum[BB * CC];
__device__ float g_KsumE[BB * CQ];                      // Ksum + EPS

// ---------------- kernel 1: Q,K projection + per-column L2 norm ----------------
__global__ __launch_bounds__(256) void qk_kernel(
    const float* __restrict__ x1, const float* __restrict__ Wq,
    const float* __restrict__ bq, const float* __restrict__ Wk,
    const float* __restrict__ bk)
{
    extern __shared__ float smem[];
    float* sX  = smem;               // [CC][64]
    float* sWt = smem + CC * TILE;   // transposed weights [kc:CC][o:64] stride 66
    const int tid = threadIdx.x;
    const int b = blockIdx.y;
    const int n0 = blockIdx.x * TILE;

    const float* xb = x1 + (size_t)b * CC * NN + n0;
    for (int i = tid; i < CC * TILE; i += 256) {
        int c = i >> 6, j = i & 63;
        sX[i] = xb[(size_t)c * NN + j];
    }
    for (int i = tid; i < 64 * CC; i += 256) {
        int o = i / CC, c = i - o * CC;
        float w = (o < CQ) ? Wq[o * CC + c] : Wk[(o - CQ) * CC + c];
        sWt[c * 66 + o] = w;
    }
    __syncthreads();

    const int ty = tid >> 4, tx = tid & 15;   // rows ty*4..ty*4+3 (2 pairs), cols tx*4..+3
    u64 accp[2][4];
    #pragma unroll
    for (int p = 0; p < 2; p++)
        #pragma unroll
        for (int e = 0; e < 4; e++) accp[p][e] = 0ull;

    const float4* sX4 = (const float4*)sX;
    #pragma unroll 4
    for (int kc = 0; kc < CC; kc++) {
        float4 xv = sX4[kc * 16 + tx];
        u64 xx0 = pack2s(xv.x), xx1 = pack2s(xv.y);
        u64 xx2 = pack2s(xv.z), xx3 = pack2s(xv.w);
        const float* wrow = sWt + kc * 66 + ty * 4;
        #pragma unroll
        for (int p = 0; p < 2; p++) {
            u64 w2 = *(const u64*)(wrow + 2 * p);   // (w[o], w[o+1]), aligned
            fma2(accp[p][0], w2, xx0);
            fma2(accp[p][1], w2, xx1);
            fma2(accp[p][2], w2, xx2);
            fma2(accp[p][3], w2, xx3);
        }
    }
    __syncthreads();   // done reading sX/sWt

    float* sQK  = smem;               // [64][68]
    float* sNrm = smem + CC * TILE;   // [128]
    #pragma unroll
    for (int p = 0; p < 2; p++) {
        int o0 = ty * 4 + 2 * p;
        float b0 = (o0 < CQ) ? __ldg(&bq[o0]) : __ldg(&bk[o0 - CQ]);
        float b1 = (o0 + 1 < CQ) ? __ldg(&bq[o0 + 1]) : __ldg(&bk[o0 + 1 - CQ]);
        #pragma unroll
        for (int jj = 0; jj < 4; jj++) {
            float2 v = unpk2(accp[p][jj]);
            sQK[o0 * 68 + tx * 4 + jj]       = v.x + b0;
            sQK[(o0 + 1) * 68 + tx * 4 + jj] = v.y + b1;
        }
    }
    __syncthreads();

    if (tid < 128) {              // 64 q-norms, 64 k-norms
        int j = tid & 63, h = tid >> 6;
        float s = 0.f;
        #pragma unroll
        for (int r = 0; r < CQ; r++) {
            float v = sQK[(h * CQ + r) * 68 + j];
            s += v * v;
        }
        sNrm[tid] = rsqrtf(s);
    }
    __syncthreads();

    float* gq = g_Qn + (size_t)(b * NN + n0) * CQ;
    for (int i = tid; i < CQ * TILE; i += 256) {   // coalesced [n][r] writes
        int j = i >> 5, r = i & 31;
        gq[i] = sQK[r * 68 + j] * sNrm[j];
    }
    for (int i = tid; i < CQ * TILE; i += 256) {   // coalesced [r][n] writes
        int r = i >> 6, j = i & 63;
        g_Kn[(size_t)(b * CQ + r) * NN + n0 + j] = sQK[(CQ + r) * 68 + j] * sNrm[64 + j];
    }
}

// ---------------- kernel 2: fused V projection + matrix/value_sum partials ----------------
__global__ __launch_bounds__(256) void vmat_kernel(
    const float* __restrict__ x, const float* __restrict__ Wv,
    const float* __restrict__ bv)
{
    extern __shared__ float smem[];
    float* sX  = smem;                  // [CC][64] (region sized CC*66 for sV reuse)
    float* sWt = smem + CC * 66;        // transposed Wv chunk [kcl:32][o:CC] stride 194
    float* sKn = sWt + 32 * 194;        // [CQ][64]
    const int tid = threadIdx.x;
    const int b = blockIdx.y;
    const int tile = blockIdx.x;
    const int n0 = tile * TILE;

    const float* xb = x + (size_t)b * CC * NN + n0;
    for (int i = tid; i < CC * TILE; i += 256) {
        int c = i >> 6, j = i & 63;
        sX[i] = xb[(size_t)c * NN + j];
    }
    for (int i = tid; i < CQ * TILE; i += 256) {
        int r = i >> 6, j = i & 63;
        sKn[i] = g_Kn[(size_t)(b * CQ + r) * NN + n0 + j];
    }

    const int ty = tid >> 4, tx = tid & 15;   // rows ty*12..ty*12+11 (6 pairs), cols tx*4..+3
    u64 accp[6][4];
    #pragma unroll
    for (int p = 0; p < 6; p++)
        #pragma unroll
        for (int e = 0; e < 4; e++) accp[p][e] = 0ull;

    const float4* sX4 = (const float4*)sX;
    for (int c0 = 0; c0 < CC; c0 += 32) {
        __syncthreads();   // (also covers the initial sX/sKn loads at c0==0)
        for (int i = tid; i < CC * 32; i += 256) {
            int o = i >> 5, kcl = i & 31;    // coalesced Wv reads
            sWt[kcl * 194 + o] = Wv[o * CC + c0 + kcl];
        }
        __syncthreads();
        #pragma unroll 2
        for (int kcl = 0; kcl < 32; kcl++) {
            float4 xv = sX4[(c0 + kcl) * 16 + tx];
            u64 xx0 = pack2s(xv.x), xx1 = pack2s(xv.y);
            u64 xx2 = pack2s(xv.z), xx3 = pack2s(xv.w);
            const float* wrow = sWt + kcl * 194 + ty * 12;
            #pragma unroll
            for (int p = 0; p < 6; p++) {
                u64 w2 = *(const u64*)(wrow + 2 * p);   // (w[o], w[o+1]), aligned
                fma2(accp[p][0], w2, xx0);
                fma2(accp[p][1], w2, xx1);
                fma2(accp[p][2], w2, xx2);
                fma2(accp[p][3], w2, xx3);
            }
        }
    }
    __syncthreads();   // done reading sX

    float* sV = smem;   // [CC][66]  (reuses sX region)
    #pragma unroll
    for (int p = 0; p < 6; p++) {
        int o0 = ty * 12 + 2 * p;
        float b0 = __ldg(&bv[o0]);
        float b1 = __ldg(&bv[o0 + 1]);
        #pragma unroll
        for (int jj = 0; jj < 4; jj++) {
            float2 v = unpk2(accp[p][jj]);
            sV[o0 * 66 + tx * 4 + jj]       = v.x + b0;
            sV[(o0 + 1) * 66 + tx * 4 + jj] = v.y + b1;
        }
    }
    __syncthreads();

    // matrix partial: mat[m][c] += sum_j Kn[m][j] * V[c][j]   (packed j-pairs)
    const int m  = tid >> 3;   // 0..31
    const int t8 = tid & 7;    // c = q*8 + t8
    u64 acc2[24];
    #pragma unroll
    for (int q = 0; q < 24; q++) acc2[q] = 0ull;

    #pragma unroll 4
    for (int j2 = 0; j2 < 32; j2++) {
        u64 kv = *(const u64*)(sKn + m * 64 + 2 * j2);          // aligned (even)
        #pragma unroll
        for (int q = 0; q < 24; q++) {
            u64 vv = *(const u64*)(sV + (q * 8 + t8) * 66 + 2 * j2);  // aligned (66 even)
            fma2(acc2[q], kv, vv);
        }
    }
    float* matp = g_MatPart + (size_t)(b * NT + tile) * (CQ * CC);
    #pragma unroll
    for (int q = 0; q < 24; q++) {
        float2 f = unpk2(acc2[q]);
        matp[m * CC + q * 8 + t8] = f.x + f.y;
    }

    if (tid < CC) {   // value_sum partial
        float s = 0.f;
        const float2* row = (const float2*)(sV + tid * 66);
        #pragma unroll 8
        for (int j2 = 0; j2 < 32; j2++) s += row[j2].x + row[j2].y;
        g_VsumPart[(size_t)(b * NT + tile) * CC + tid] = s;
    }
}

// ---------------- deterministic reductions ----------------
__global__ __launch_bounds__(256) void ksum_kernel()
{
    const int r = blockIdx.x, b = blockIdx.y;
    const float* p = g_Kn + (size_t)(b * CQ + r) * NN;
    float s = 0.f;
    for (int i = threadIdx.x; i < NN; i += 256) s += p[i];
    __shared__ float red[256];
    red[threadIdx.x] = s;
    __syncthreads();
    for (int st = 128; st > 0; st >>= 1) {
        if (threadIdx.x < st) red[threadIdx.x] += red[threadIdx.x + st];
        __syncthreads();
    }
    if (threadIdx.x == 0) g_KsumE[b * CQ + r] = red[0] + 1e-6f;
}

__global__ __launch_bounds__(256) void matred_kernel()
{
    const int b = blockIdx.y;
    const int i = blockIdx.x * 256 + threadIdx.x;   // < CQ*CC = 6144
    const float* p = g_MatPart + (size_t)b * NT * (CQ * CC) + i;
    float s = 0.f;
    for (int t = 0; t < NT; t++) s += p[(size_t)t * (CQ * CC)];
    g_Mat[b * CQ * CC + i] = s;
}

__global__ __launch_bounds__(192) void vsumred_kernel()
{
    const int b = blockIdx.x;
    const int c = threadIdx.x;   // < 192
    const float* p = g_VsumPart + (size_t)b * NT * CC + c;
    float s = 0.f;
    for (int t = 0; t < NT; t++) s += p[(size_t)t * CC];
    g_Vsum[b * CC + c] = s;
}

// ---------------- kernel 6: epilogue ----------------
__global__ __launch_bounds__(256) void final_kernel(
    const float* __restrict__ gamma, float* __restrict__ out)
{
    __shared__ float sQn[TILE * 33];    // [j][r] padded
    __shared__ float sMatT[CC * 34];    // transposed matrix [c][r] stride 34 (even)
    __shared__ float sVs[CC];
    __shared__ float sKs[CQ];
    __shared__ float sTail[TILE];
    const int tid = threadIdx.x;
    const int b = blockIdx.y;
    const int n0 = blockIdx.x * TILE;

    const float* gq = g_Qn + (size_t)(b * NN + n0) * CQ;
    for (int i = tid; i < TILE * CQ; i += 256) {
        int j = i >> 5, r = i & 31;
        sQn[j * 33 + r] = gq[i];
    }
    for (int i = tid; i < CQ * CC; i += 256) {   // coalesced read, transposed store
        int r = i / CC, c = i - r * CC;
        sMatT[c * 34 + r] = g_Mat[b * CQ * CC + i];
    }
    if (tid < CC) sVs[tid] = g_Vsum[b * CC + tid];
    if (tid < CQ) sKs[tid] = g_KsumE[b * CQ + tid];
    __syncthreads();

    if (tid < TILE) {
        float s = 0.f;
        #pragma unroll
        for (int r = 0; r < CQ; r++) s += sQn[tid * 33 + r] * sKs[r];
        sTail[tid] = 1.0f / ((float)NN + s);
    }
    __syncthreads();

    const float g = __ldg(gamma);
    const int j = tid & 63, cy = tid >> 6;   // warp: 32 consecutive j, same cy
    u64 q2[CQ / 2];
    #pragma unroll
    for (int r2 = 0; r2 < CQ / 2; r2++)
        q2[r2] = pack2(sQn[j * 33 + 2 * r2], sQn[j * 33 + 2 * r2 + 1]);
    const float tl = sTail[j] * g;

    float* ob = out + (size_t)b * CC * NN + n0 + j;
    for (int c = cy; c < CC; c += 4) {
        u64 a2 = 0ull;
        const u64* mrow = (const u64*)(sMatT + c * 34);   // broadcast within warp
        #pragma unroll
        for (int r2 = 0; r2 < CQ / 2; r2++) fma2(a2, q2[r2], mrow[r2]);
        float2 f = unpk2(a2);
        ob[(size_t)c * NN] = (sVs[c] + f.x + f.y) * tl;   // coalesced over j
    }
}

// ---------------- launch ----------------
extern "C" void kernel_launch(void* const* d_in, const int* in_sizes, int n_in,
                              void* d_out, int out_size)
{
    const float* x  = (const float*)d_in[0];
    const float* x1 = (const float*)d_in[1];
    const float* Wq = (const float*)d_in[2];
    const float* bq = (const float*)d_in[3];
    const float* Wk = (const float*)d_in[4];
    const float* bk = (const float*)d_in[5];
    const float* Wv = (const float*)d_in[6];
    const float* bv = (const float*)d_in[7];
    const float* gm = (const float*)d_in[8];
    float* out = (float*)d_out;

    const int smemQK = (CC * TILE + CC * 66) * 4;              // ~97.5 KB
    const int smemV  = (CC * 66 + 32 * 194 + CQ * TILE) * 4;   // ~83.7 KB
    cudaFuncSetAttribute(qk_kernel,   cudaFuncAttributeMaxDynamicSharedMemorySize, smemQK);
    cudaFuncSetAttribute(vmat_kernel, cudaFuncAttributeMaxDynamicSharedMemorySize, smemV);

    dim3 grid(NT, BB);
    qk_kernel<<<grid, 256, smemQK>>>(x1, Wq, bq, Wk, bk);
    vmat_kernel<<<grid, 256, smemV>>>(x, Wv, bv);
    ksum_kernel<<<dim3(CQ, BB), 256>>>();
    matred_kernel<<<dim3((CQ * CC) / 256, BB), 256>>>();
    vsumred_kernel<<<BB, 192>>>();
    final_kernel<<<grid, 256>>>(gm, out);
}

// round 6
// speedup vs baseline: 1.3995x; 1.3995x over previous
#include <cuda_runtime.h>
#include <cuda_bf16.h>
#include <cstdint>

#define BB 8
#define CC 192
#define CQ 32
#define NN 16384
#define TILE 64
#define NT (NN / TILE)      // 256 tiles (qk / final)
#define TV 64
#define NTV (NN / TV)       // 256 tiles (vmat)

// ---------------- scratch (static device globals; no allocations) ----------------
__device__ float g_Qn[(size_t)BB * NN * CQ];            // [b][n][r]
__device__ float g_Kn[(size_t)BB * CQ * NN];            // [b][r][n]
__device__ float g_MatPart[(size_t)BB * NTV * CQ * CC];
__device__ float g_VsumPart[(size_t)BB * NTV * CC];
__device__ float g_Mat[BB * CQ * CC];
__device__ float g_Vsum[BB * CC];
__device__ float g_KsumE[BB * CQ];                      // Ksum + EPS

// ---------------- warp MMA helpers (baseline PTX, sm_80+: no 'a'-target needed) ----------------
__device__ __forceinline__ uint32_t s2u(const void* p) {
    uint32_t a;
    asm("{ .reg .u64 t; cvta.to.shared.u64 t, %1; cvt.u32.u64 %0, t; }" : "=r"(a) : "l"(p));
    return a;
}
__device__ __forceinline__ void ldm4(uint32_t* r, uint32_t a) {
    asm volatile("ldmatrix.sync.aligned.m8n8.x4.shared.b16 {%0,%1,%2,%3}, [%4];"
                 : "=r"(r[0]), "=r"(r[1]), "=r"(r[2]), "=r"(r[3]) : "r"(a));
}
__device__ __forceinline__ void ldm2(uint32_t* r, uint32_t a) {
    asm volatile("ldmatrix.sync.aligned.m8n8.x2.shared.b16 {%0,%1}, [%2];"
                 : "=r"(r[0]), "=r"(r[1]) : "r"(a));
}
__device__ __forceinline__ void ldm2t(uint32_t* r, uint32_t a) {
    asm volatile("ldmatrix.sync.aligned.m8n8.x2.trans.shared.b16 {%0,%1}, [%2];"
                 : "=r"(r[0]), "=r"(r[1]) : "r"(a));
}
__device__ __forceinline__ void mma16816(float* d, const uint32_t* a, const uint32_t* b) {
    asm volatile("mma.sync.aligned.m16n8k16.row.col.f32.bf16.bf16.f32 "
                 "{%0,%1,%2,%3},{%4,%5,%6,%7},{%8,%9},{%0,%1,%2,%3};"
                 : "+f"(d[0]), "+f"(d[1]), "+f"(d[2]), "+f"(d[3])
                 : "r"(a[0]), "r"(a[1]), "r"(a[2]), "r"(a[3]), "r"(b[0]), "r"(b[1]));
}
__device__ __forceinline__ void bsplit(float v, uint16_t& h, uint16_t& l) {
    __nv_bfloat16 hb = __float2bfloat16(v);
    __nv_bfloat16 lb = __float2bfloat16(v - __bfloat162float(hb));
    h = *(uint16_t*)&hb;
    l = *(uint16_t*)&lb;
}
__device__ __forceinline__ uint32_t bpack2(float a, float b) {   // low half = a
    __nv_bfloat162 t = __floats2bfloat162_rn(a, b);
    return *(uint32_t*)&t;
}

// ---------------- kernel 1: Q,K projection + per-column L2 norm (scalar, R2) ----------------
__global__ __launch_bounds__(256) void qk_kernel(
    const float* __restrict__ x1, const float* __restrict__ Wq,
    const float* __restrict__ bq, const float* __restrict__ Wk,
    const float* __restrict__ bk)
{
    extern __shared__ float smem[];
    float* sX = smem;               // [CC][64]
    float* sW = smem + CC * TILE;   // [64][CC]
    const int tid = threadIdx.x;
    const int b = blockIdx.y;
    const int n0 = blockIdx.x * TILE;

    const float* xb = x1 + (size_t)b * CC * NN + n0;
    for (int i = tid; i < CC * TILE; i += 256) {
        int c = i >> 6, j = i & 63;
        sX[i] = xb[(size_t)c * NN + j];
    }
    for (int i = tid; i < 64 * CC; i += 256) {
        int o = i / CC, c = i - o * CC;
        sW[i] = (o < CQ) ? Wq[o * CC + c] : Wk[(o - CQ) * CC + c];
    }
    __syncthreads();

    const int ty = tid >> 4, tx = tid & 15;
    float acc[4][4];
    #pragma unroll
    for (int a = 0; a < 4; a++)
        #pragma unroll
        for (int e = 0; e < 4; e++) acc[a][e] = 0.f;

    const float4* sX4 = (const float4*)sX;
    #pragma unroll 4
    for (int kc = 0; kc < CC; kc++) {
        float4 xv = sX4[kc * 16 + tx];
        #pragma unroll
        for (int oo = 0; oo < 4; oo++) {
            float w = sW[(ty * 4 + oo) * CC + kc];
            acc[oo][0] += w * xv.x;
            acc[oo][1] += w * xv.y;
            acc[oo][2] += w * xv.z;
            acc[oo][3] += w * xv.w;
        }
    }
    #pragma unroll
    for (int oo = 0; oo < 4; oo++) {
        int o = ty * 4 + oo;
        float bias = (o < CQ) ? __ldg(&bq[o]) : __ldg(&bk[o - CQ]);
        #pragma unroll
        for (int jj = 0; jj < 4; jj++) acc[oo][jj] += bias;
    }
    __syncthreads();

    float* sQK  = smem;
    float* sNrm = smem + CC * TILE;
    #pragma unroll
    for (int oo = 0; oo < 4; oo++)
        #pragma unroll
        for (int jj = 0; jj < 4; jj++)
            sQK[(ty * 4 + oo) * 68 + tx * 4 + jj] = acc[oo][jj];
    __syncthreads();

    if (tid < 128) {
        int j = tid & 63, h = tid >> 6;
        float s = 0.f;
        #pragma unroll
        for (int r = 0; r < CQ; r++) {
            float v = sQK[(h * CQ + r) * 68 + j];
            s += v * v;
        }
        sNrm[tid] = rsqrtf(s);
    }
    __syncthreads();

    float* gq = g_Qn + (size_t)(b * NN + n0) * CQ;
    for (int i = tid; i < CQ * TILE; i += 256) {
        int j = i >> 5, r = i & 31;
        gq[i] = sQK[r * 68 + j] * sNrm[j];
    }
    for (int i = tid; i < CQ * TILE; i += 256) {
        int r = i >> 6, j = i & 63;
        g_Kn[(size_t)(b * CQ + r) * NN + n0 + j] = sQK[(CQ + r) * 68 + j] * sNrm[64 + j];
    }
}

// ---------------- kernel 2: mma.sync bf16-split V GEMM + matrix/value_sum partials ----------------
// smem layout (bytes); all strides 72 bf16 elems = 144 B (ldmatrix conflict-free, %8 units = 1)
#define SMV_XH 0            // X hi [192 c][72]  -> later V hi [192 c][72]
#define SMV_XL 27648        // X lo              -> later V lo
#define SMV_WH 55296        // Wv chunk hi [192 o][72] -> later Kn_pad hi [48 m][72]
#define SMV_WL 82944        // Wv chunk lo             -> later Kn_pad lo
#define SMV_BV 110592       // bv f32 [192]
#define SMV_TOT 111616

__global__ __launch_bounds__(256) void vmat_mma_kernel(
    const float* __restrict__ x, const float* __restrict__ Wv,
    const float* __restrict__ bv)
{
    extern __shared__ char sm[];
    const uint32_t sb = s2u(sm);
    const int tid = threadIdx.x;
    const int lane = tid & 31;
    const int wid = tid >> 5;
    const int ln16 = lane & 15;
    const int b = blockIdx.y;
    const int tile = blockIdx.x;
    const int n0 = tile * TV;

    float* sBv = (float*)(sm + SMV_BV);
    if (tid < CC) sBv[tid] = bv[tid];

    // ---- X tile -> bf16 hi/lo, [c][j] row-major (144B rows) ----
    const float* xb = x + (size_t)b * CC * NN + n0;
    for (int i = tid; i < CC * TV; i += 256) {
        int c = i >> 6, j = i & 63;
        float v = xb[(size_t)c * NN + j];
        uint16_t h, l; bsplit(v, h, l);
        *(uint16_t*)(sm + SMV_XH + (c * 72 + j) * 2) = h;
        *(uint16_t*)(sm + SMV_XL + (c * 72 + j) * 2) = l;
    }

    // ---- GEMM1: D1[o:192][j:64] = Wv · X ; warp grid 4(M=48) x 2(N=32) ----
    const int wm = wid & 3, wn = wid >> 2;
    float d1[3][4][4];
    #pragma unroll
    for (int mt = 0; mt < 3; mt++)
        #pragma unroll
        for (int nt = 0; nt < 4; nt++)
            #pragma unroll
            for (int e = 0; e < 4; e++) d1[mt][nt][e] = 0.f;

    for (int ch = 0; ch < 3; ch++) {            // K chunks of 64 channels
        __syncthreads();                         // prev-chunk readers done (also covers X writes)
        const int c0 = ch * 64;
        for (int i = tid; i < CC * 64; i += 256) {
            int o = i >> 6, cl = i & 63;
            float w = Wv[o * CC + c0 + cl];
            uint16_t h, l; bsplit(w, h, l);
            *(uint16_t*)(sm + SMV_WH + (o * 72 + cl) * 2) = h;
            *(uint16_t*)(sm + SMV_WL + (o * 72 + cl) * 2) = l;
        }
        __syncthreads();
        #pragma unroll
        for (int ks = 0; ks < 4; ks++) {         // k-subtiles of 16
            uint32_t ah[3][4], al[3][4];
            const int acol = ks * 16 + (lane >> 4) * 8;
            #pragma unroll
            for (int mt = 0; mt < 3; mt++) {
                uint32_t off = (uint32_t)(((wm * 48 + mt * 16 + ln16) * 72 + acol) * 2);
                ldm4(ah[mt], sb + SMV_WH + off);
                ldm4(al[mt], sb + SMV_WL + off);
            }
            uint32_t bh[4][2], bl[4][2];
            const int brow = c0 + ks * 16 + ln16;       // k rows in X
            #pragma unroll
            for (int nt = 0; nt < 4; nt++) {
                uint32_t off = (uint32_t)((brow * 72 + wn * 32 + nt * 8) * 2);
                ldm2t(bh[nt], sb + SMV_XH + off);
                ldm2t(bl[nt], sb + SMV_XL + off);
            }
            #pragma unroll
            for (int mt = 0; mt < 3; mt++)
                #pragma unroll
                for (int nt = 0; nt < 4; nt++) {
                    mma16816(d1[mt][nt], ah[mt], bh[nt]);
                    mma16816(d1[mt][nt], ah[mt], bl[nt]);
                    mma16816(d1[mt][nt], al[mt], bh[nt]);
                }
        }
    }
    __syncthreads();   // all GEMM1 reads of sX/sW complete

    // ---- zero Kn_pad region (48 rows x 72), disjoint from V writes ----
    for (int i = tid; i < 48 * 72 / 2; i += 256) {       // u32 over u16 pairs
        ((uint32_t*)(sm + SMV_WH))[i] = 0u;
        ((uint32_t*)(sm + SMV_WL))[i] = 0u;
    }

    // ---- epilogue: V = D1 + bv, bf16-split into [c][j] (reuses X region) ----
    #pragma unroll
    for (int mt = 0; mt < 3; mt++) {
        const int o0 = wm * 48 + mt * 16 + (lane >> 2);
        #pragma unroll
        for (int nt = 0; nt < 4; nt++) {
            const int j0 = wn * 32 + nt * 8 + (lane & 3) * 2;
            const float* d = d1[mt][nt];
            #pragma unroll
            for (int rr = 0; rr < 2; rr++) {
                const int o = o0 + rr * 8;
                float v0 = d[rr * 2 + 0] + sBv[o];
                float v1 = d[rr * 2 + 1] + sBv[o];
                float h0 = __bfloat162float(__float2bfloat16(v0));
                float h1 = __bfloat162float(__float2bfloat16(v1));
                *(uint32_t*)(sm + SMV_XH + (o * 72 + j0) * 2) = bpack2(v0, v1);
                *(uint32_t*)(sm + SMV_XL + (o * 72 + j0) * 2) = bpack2(v0 - h0, v1 - h1);
            }
        }
    }
    __syncthreads();

    // ---- Kn_pad: rows 0-31 = Kn tile, row 32 = ones (value_sum), 33-47 zero ----
    for (int i = tid; i < CQ * TV; i += 256) {
        int m = i >> 6, j = i & 63;
        float v = g_Kn[(size_t)(b * CQ + m) * NN + n0 + j];
        uint16_t h, l; bsplit(v, h, l);
        *(uint16_t*)(sm + SMV_WH + (m * 72 + j) * 2) = h;
        *(uint16_t*)(sm + SMV_WL + (m * 72 + j) * 2) = l;
    }
    if (tid < TV)
        *(uint16_t*)(sm + SMV_WH + (32 * 72 + tid) * 2) = 0x3F80;   // bf16 1.0
    __syncthreads();

    // ---- GEMM2: D2[m:48][c:192] = Kn_pad · V^T ; warp w covers c in [w*24, w*24+24) ----
    float d2[3][3][4];
    #pragma unroll
    for (int mt = 0; mt < 3; mt++)
        #pragma unroll
        for (int nt = 0; nt < 3; nt++)
            #pragma unroll
            for (int e = 0; e < 4; e++) d2[mt][nt][e] = 0.f;

    const int n0w = wid * 24;
    #pragma unroll
    for (int ks = 0; ks < 4; ks++) {             // k = j, 4 subtiles of 16
        uint32_t ah[3][4], al[3][4];
        const int acol = ks * 16 + (lane >> 4) * 8;
        #pragma unroll
        for (int mt = 0; mt < 3; mt++) {
            uint32_t off = (uint32_t)(((mt * 16 + ln16) * 72 + acol) * 2);
            ldm4(ah[mt], sb + SMV_WH + off);
            ldm4(al[mt], sb + SMV_WL + off);
        }
        uint32_t bh[3][2], bl[3][2];
        #pragma unroll
        for (int nt = 0; nt < 3; nt++) {
            const int crow = n0w + nt * 8 + (lane & 7);
            const int kcol = ks * 16 + ((lane >> 3) & 1) * 8;
            uint32_t off = (uint32_t)((crow * 72 + kcol) * 2);
            ldm2(bh[nt], sb + SMV_XH + off);
            ldm2(bl[nt], sb + SMV_XL + off);
        }
        #pragma unroll
        for (int mt = 0; mt < 3; mt++)
            #pragma unroll
            for (int nt = 0; nt < 3; nt++) {
                mma16816(d2[mt][nt], ah[mt], bh[nt]);
                mma16816(d2[mt][nt], ah[mt], bl[nt]);
                mma16816(d2[mt][nt], al[mt], bh[nt]);
            }
    }

    // ---- write partials: rows 0-31 -> matrix, row 32 -> value_sum ----
    float* matp = g_MatPart + (size_t)(b * NTV + tile) * (CQ * CC);
    float* vsp  = g_VsumPart + (size_t)(b * NTV + tile) * CC;
    #pragma unroll
    for (int mt = 0; mt < 3; mt++) {
        const int r0 = mt * 16 + (lane >> 2);
        #pragma unroll
        for (int nt = 0; nt < 3; nt++) {
            const int c0w = n0w + nt * 8 + (lane & 3) * 2;
            const float* d = d2[mt][nt];
            #pragma unroll
            for (int rr = 0; rr < 2; rr++) {
                const int r = r0 + rr * 8;
                if (r < 32) {
                    matp[r * CC + c0w]     = d[rr * 2 + 0];
                    matp[r * CC + c0w + 1] = d[rr * 2 + 1];
                } else if (r == 32) {
                    vsp[c0w]     = d[rr * 2 + 0];
                    vsp[c0w + 1] = d[rr * 2 + 1];
                }
            }
        }
    }
}

// ---------------- deterministic reductions ----------------
__global__ __launch_bounds__(256) void ksum_kernel()
{
    const int r = blockIdx.x, b = blockIdx.y;
    const float* p = g_Kn + (size_t)(b * CQ + r) * NN;
    float s = 0.f;
    for (int i = threadIdx.x; i < NN; i += 256) s += p[i];
    __shared__ float red[256];
    red[threadIdx.x] = s;
    __syncthreads();
    for (int st = 128; st > 0; st >>= 1) {
        if (threadIdx.x < st) red[threadIdx.x] += red[threadIdx.x + st];
        __syncthreads();
    }
    if (threadIdx.x == 0) g_KsumE[b * CQ + r] = red[0] + 1e-6f;
}

__global__ __launch_bounds__(256) void matred_kernel()
{
    const int b = blockIdx.y;
    const int i = blockIdx.x * 256 + threadIdx.x;   // < CQ*CC
    const float* p = g_MatPart + (size_t)b * NTV * (CQ * CC) + i;
    float s = 0.f;
    for (int t = 0; t < NTV; t++) s += p[(size_t)t * (CQ * CC)];
    g_Mat[b * CQ * CC + i] = s;
}

__global__ __launch_bounds__(192) void vsumred_kernel()
{
    const int b = blockIdx.x;
    const int c = threadIdx.x;
    const float* p = g_VsumPart + (size_t)b * NTV * CC + c;
    float s = 0.f;
    for (int t = 0; t < NTV; t++) s += p[(size_t)t * CC];
    g_Vsum[b * CC + c] = s;
}

// ---------------- kernel 6: epilogue (scalar, R2) ----------------
__global__ __launch_bounds__(256) void final_kernel(
    const float* __restrict__ gamma, float* __restrict__ out)
{
    __shared__ float sQn[TILE * 33];
    __shared__ float sMat[CQ * CC];
    __shared__ float sVs[CC];
    __shared__ float sKs[CQ];
    __shared__ float sTail[TILE];
    const int tid = threadIdx.x;
    const int b = blockIdx.y;
    const int n0 = blockIdx.x * TILE;

    const float* gq = g_Qn + (size_t)(b * NN + n0) * CQ;
    for (int i = tid; i < TILE * CQ; i += 256) {
        int j = i >> 5, r = i & 31;
        sQn[j * 33 + r] = gq[i];
    }
    for (int i = tid; i < CQ * CC; i += 256) sMat[i] = g_Mat[b * CQ * CC + i];
    if (tid < CC) sVs[tid] = g_Vsum[b * CC + tid];
    if (tid < CQ) sKs[tid] = g_KsumE[b * CQ + tid];
    __syncthreads();

    if (tid < TILE) {
        float s = 0.f;
        #pragma unroll
        for (int r = 0; r < CQ; r++) s += sQn[tid * 33 + r] * sKs[r];
        sTail[tid] = 1.0f / ((float)NN + s);
    }
    __syncthreads();

    const float g = __ldg(gamma);
    const int j = tid & 63, cy = tid >> 6;
    float q[CQ];
    #pragma unroll
    for (int r = 0; r < CQ; r++) q[r] = sQn[j * 33 + r];
    const float tl = sTail[j] * g;

    float* ob = out + (size_t)b * CC * NN + n0 + j;
    for (int c = cy; c < CC; c += 4) {
        float a = sVs[c];
        #pragma unroll
        for (int r = 0; r < CQ; r++) a += q[r] * sMat[r * CC + c];
        ob[(size_t)c * NN] = a * tl;
    }
}

// ---------------- launch ----------------
extern "C" void kernel_launch(void* const* d_in, const int* in_sizes, int n_in,
                              void* d_out, int out_size)
{
    const float* x  = (const float*)d_in[0];
    const float* x1 = (const float*)d_in[1];
    const float* Wq = (const float*)d_in[2];
    const float* bq = (const float*)d_in[3];
    const float* Wk = (const float*)d_in[4];
    const float* bk = (const float*)d_in[5];
    const float* Wv = (const float*)d_in[6];
    const float* bv = (const float*)d_in[7];
    const float* gm = (const float*)d_in[8];
    float* out = (float*)d_out;

    const int smemQK = (CC * TILE + 64 * CC) * 4;   // 96 KB
    cudaFuncSetAttribute(qk_kernel,       cudaFuncAttributeMaxDynamicSharedMemorySize, smemQK);
    cudaFuncSetAttribute(vmat_mma_kernel, cudaFuncAttributeMaxDynamicSharedMemorySize, SMV_TOT);

    qk_kernel<<<dim3(NT, BB), 256, smemQK>>>(x1, Wq, bq, Wk, bk);
    vmat_mma_kernel<<<dim3(NTV, BB), 256, SMV_TOT>>>(x, Wv, bv);
    ksum_kernel<<<dim3(CQ, BB), 256>>>();
    matred_kernel<<<dim3((CQ * CC) / 256, BB), 256>>>();
    vsumred_kernel<<<BB, 192>>>();
    final_kernel<<<dim3(NT, BB), 256>>>(gm, out);
}

// round 7
// speedup vs baseline: 1.5759x; 1.1260x over previous
#include <cuda_runtime.h>
#include <cuda_bf16.h>
#include <cstdint>

#define BB 8
#define CC 192
#define CQ 32
#define NN 16384
#define TILE 64
#define NT (NN / TILE)      // 256 tiles
#define TV 64
#define NTV (NN / TV)       // 256 tiles (vmat)

// ---------------- scratch (static device globals; no allocations) ----------------
__device__ float g_Qn[(size_t)BB * NN * CQ];            // [b][n][r]
__device__ float g_Kn[(size_t)BB * CQ * NN];            // [b][r][n]
__device__ float g_MatPart[(size_t)BB * NTV * CQ * CC];
__device__ float g_VsumPart[(size_t)BB * NTV * CC];
__device__ float g_Mat[BB * CQ * CC];
__device__ float g_Vsum[BB * CC];
__device__ float g_KsumE[BB * CQ];                      // Ksum + EPS

// ---------------- warp MMA helpers (baseline PTX, sm_80+) ----------------
__device__ __forceinline__ uint32_t s2u(const void* p) {
    uint32_t a;
    asm("{ .reg .u64 t; cvta.to.shared.u64 t, %1; cvt.u32.u64 %0, t; }" : "=r"(a) : "l"(p));
    return a;
}
__device__ __forceinline__ void ldm4(uint32_t* r, uint32_t a) {
    asm volatile("ldmatrix.sync.aligned.m8n8.x4.shared.b16 {%0,%1,%2,%3}, [%4];"
                 : "=r"(r[0]), "=r"(r[1]), "=r"(r[2]), "=r"(r[3]) : "r"(a));
}
__device__ __forceinline__ void ldm2(uint32_t* r, uint32_t a) {
    asm volatile("ldmatrix.sync.aligned.m8n8.x2.shared.b16 {%0,%1}, [%2];"
                 : "=r"(r[0]), "=r"(r[1]) : "r"(a));
}
__device__ __forceinline__ void ldm2t(uint32_t* r, uint32_t a) {
    asm volatile("ldmatrix.sync.aligned.m8n8.x2.trans.shared.b16 {%0,%1}, [%2];"
                 : "=r"(r[0]), "=r"(r[1]) : "r"(a));
}
__device__ __forceinline__ void mma16816(float* d, const uint32_t* a, const uint32_t* b) {
    asm volatile("mma.sync.aligned.m16n8k16.row.col.f32.bf16.bf16.f32 "
                 "{%0,%1,%2,%3},{%4,%5,%6,%7},{%8,%9},{%0,%1,%2,%3};"
                 : "+f"(d[0]), "+f"(d[1]), "+f"(d[2]), "+f"(d[3])
                 : "r"(a[0]), "r"(a[1]), "r"(a[2]), "r"(a[3]), "r"(b[0]), "r"(b[1]));
}
__device__ __forceinline__ void bsplit(float v, uint16_t& h, uint16_t& l) {
    __nv_bfloat16 hb = __float2bfloat16(v);
    __nv_bfloat16 lb = __float2bfloat16(v - __bfloat162float(hb));
    h = *(uint16_t*)&hb;
    l = *(uint16_t*)&lb;
}
__device__ __forceinline__ uint32_t bpack2(float a, float b) {   // low half = a
    __nv_bfloat162 t = __floats2bfloat162_rn(a, b);
    return *(uint32_t*)&t;
}
__device__ __forceinline__ float bf16u(uint16_t u) {
    __nv_bfloat16 t = *(__nv_bfloat16*)&u;
    return __bfloat162float(t);
}

// ---------------- kernel 1: Q,K projection via mma.sync + per-column L2 norm ----------------
// smem (bytes): X hi/lo [192 c][72 j], W hi/lo [64 o][200 c], staging f32 [64 o][72 j] (reuses W)
#define SQ_XH 0
#define SQ_XL 27648
#define SQ_WH 55296
#define SQ_WL 80896
#define SQ_ST 55296
#define SQ_B  106496
#define SQ_NRM 106752
#define SQ_TOT 107264

__global__ __launch_bounds__(256) void qk_mma_kernel(
    const float* __restrict__ x1, const float* __restrict__ Wq,
    const float* __restrict__ bq, const float* __restrict__ Wk,
    const float* __restrict__ bk)
{
    extern __shared__ char sm[];
    const uint32_t sb = s2u(sm);
    const int tid = threadIdx.x;
    const int lane = tid & 31;
    const int wid = tid >> 5;
    const int ln16 = lane & 15;
    const int b = blockIdx.y;
    const int n0 = blockIdx.x * TILE;

    float* sB = (float*)(sm + SQ_B);
    if (tid < 64) sB[tid] = (tid < CQ) ? bq[tid] : bk[tid - CQ];

    const float* xb = x1 + (size_t)b * CC * NN + n0;
    for (int i = tid; i < CC * TILE; i += 256) {
        int c = i >> 6, j = i & 63;
        float v = xb[(size_t)c * NN + j];
        uint16_t h, l; bsplit(v, h, l);
        *(uint16_t*)(sm + SQ_XH + (c * 72 + j) * 2) = h;
        *(uint16_t*)(sm + SQ_XL + (c * 72 + j) * 2) = l;
    }
    for (int i = tid; i < 64 * CC; i += 256) {
        int o = i / CC, c = i - o * CC;
        float w = (o < CQ) ? Wq[o * CC + c] : Wk[(o - CQ) * CC + c];
        uint16_t h, l; bsplit(w, h, l);
        *(uint16_t*)(sm + SQ_WH + (o * 200 + c) * 2) = h;
        *(uint16_t*)(sm + SQ_WL + (o * 200 + c) * 2) = l;
    }
    __syncthreads();

    // D[o:64][j:64] = Wqk · X, K=192; warp grid 2(M=32) x 4(N=16)
    const int wm = wid & 1, wn = wid >> 1;
    float d[2][2][4];
    #pragma unroll
    for (int mt = 0; mt < 2; mt++)
        #pragma unroll
        for (int nt = 0; nt < 2; nt++)
            #pragma unroll
            for (int e = 0; e < 4; e++) d[mt][nt][e] = 0.f;

    #pragma unroll
    for (int ks = 0; ks < 12; ks++) {
        uint32_t ah[2][4], al[2][4];
        const int acol = ks * 16 + (lane >> 4) * 8;
        #pragma unroll
        for (int mt = 0; mt < 2; mt++) {
            uint32_t off = (uint32_t)(((wm * 32 + mt * 16 + ln16) * 200 + acol) * 2);
            ldm4(ah[mt], sb + SQ_WH + off);
            ldm4(al[mt], sb + SQ_WL + off);
        }
        uint32_t bh[2][2], bl[2][2];
        const int brow = ks * 16 + ln16;
        #pragma unroll
        for (int nt = 0; nt < 2; nt++) {
            uint32_t off = (uint32_t)((brow * 72 + wn * 16 + nt * 8) * 2);
            ldm2t(bh[nt], sb + SQ_XH + off);
            ldm2t(bl[nt], sb + SQ_XL + off);
        }
        #pragma unroll
        for (int mt = 0; mt < 2; mt++)
            #pragma unroll
            for (int nt = 0; nt < 2; nt++) {
                mma16816(d[mt][nt], ah[mt], bh[nt]);
                mma16816(d[mt][nt], ah[mt], bl[nt]);
                mma16816(d[mt][nt], al[mt], bh[nt]);
            }
    }
    __syncthreads();   // GEMM reads done; W region becomes staging

    float* sST = (float*)(sm + SQ_ST);   // [64 o][72 j]
    #pragma unroll
    for (int mt = 0; mt < 2; mt++) {
        const int o0 = wm * 32 + mt * 16 + (lane >> 2);
        #pragma unroll
        for (int nt = 0; nt < 2; nt++) {
            const int j0 = wn * 16 + nt * 8 + (lane & 3) * 2;
            #pragma unroll
            for (int rr = 0; rr < 2; rr++) {
                const int o = o0 + rr * 8;
                sST[o * 72 + j0]     = d[mt][nt][rr * 2 + 0] + sB[o];
                sST[o * 72 + j0 + 1] = d[mt][nt][rr * 2 + 1] + sB[o];
            }
        }
    }
    __syncthreads();

    float* sNrm = (float*)(sm + SQ_NRM);
    if (tid < 128) {
        int j = tid & 63, h = tid >> 6;
        float s = 0.f;
        #pragma unroll
        for (int r = 0; r < CQ; r++) {
            float v = sST[(h * CQ + r) * 72 + j];
            s += v * v;
        }
        sNrm[tid] = rsqrtf(s);
    }
    __syncthreads();

    float* gq = g_Qn + (size_t)(b * NN + n0) * CQ;
    for (int i = tid; i < CQ * TILE; i += 256) {
        int j = i >> 5, r = i & 31;
        gq[i] = sST[r * 72 + j] * sNrm[j];
    }
    for (int i = tid; i < CQ * TILE; i += 256) {
        int r = i >> 6, j = i & 63;
        g_Kn[(size_t)(b * CQ + r) * NN + n0 + j] = sST[(CQ + r) * 72 + j] * sNrm[64 + j];
    }
}

// ---------------- kernel 2: mma.sync bf16-split V GEMM + matrix/value_sum partials (R5, proven) ----------------
#define SMV_XH 0
#define SMV_XL 27648
#define SMV_WH 55296
#define SMV_WL 82944
#define SMV_BV 110592
#define SMV_TOT 111616

__global__ __launch_bounds__(256) void vmat_mma_kernel(
    const float* __restrict__ x, const float* __restrict__ Wv,
    const float* __restrict__ bv)
{
    extern __shared__ char sm[];
    const uint32_t sb = s2u(sm);
    const int tid = threadIdx.x;
    const int lane = tid & 31;
    const int wid = tid >> 5;
    const int ln16 = lane & 15;
    const int b = blockIdx.y;
    const int tile = blockIdx.x;
    const int n0 = tile * TV;

    float* sBv = (float*)(sm + SMV_BV);
    if (tid < CC) sBv[tid] = bv[tid];

    const float* xb = x + (size_t)b * CC * NN + n0;
    for (int i = tid; i < CC * TV; i += 256) {
        int c = i >> 6, j = i & 63;
        float v = xb[(size_t)c * NN + j];
        uint16_t h, l; bsplit(v, h, l);
        *(uint16_t*)(sm + SMV_XH + (c * 72 + j) * 2) = h;
        *(uint16_t*)(sm + SMV_XL + (c * 72 + j) * 2) = l;
    }

    const int wm = wid & 3, wn = wid >> 2;
    float d1[3][4][4];
    #pragma unroll
    for (int mt = 0; mt < 3; mt++)
        #pragma unroll
        for (int nt = 0; nt < 4; nt++)
            #pragma unroll
            for (int e = 0; e < 4; e++) d1[mt][nt][e] = 0.f;

    for (int ch = 0; ch < 3; ch++) {
        __syncthreads();
        const int c0 = ch * 64;
        for (int i = tid; i < CC * 64; i += 256) {
            int o = i >> 6, cl = i & 63;
            float w = Wv[o * CC + c0 + cl];
            uint16_t h, l; bsplit(w, h, l);
            *(uint16_t*)(sm + SMV_WH + (o * 72 + cl) * 2) = h;
            *(uint16_t*)(sm + SMV_WL + (o * 72 + cl) * 2) = l;
        }
        __syncthreads();
        #pragma unroll
        for (int ks = 0; ks < 4; ks++) {
            uint32_t ah[3][4], al[3][4];
            const int acol = ks * 16 + (lane >> 4) * 8;
            #pragma unroll
            for (int mt = 0; mt < 3; mt++) {
                uint32_t off = (uint32_t)(((wm * 48 + mt * 16 + ln16) * 72 + acol) * 2);
                ldm4(ah[mt], sb + SMV_WH + off);
                ldm4(al[mt], sb + SMV_WL + off);
            }
            uint32_t bh[4][2], bl[4][2];
            const int brow = c0 + ks * 16 + ln16;
            #pragma unroll
            for (int nt = 0; nt < 4; nt++) {
                uint32_t off = (uint32_t)((brow * 72 + wn * 32 + nt * 8) * 2);
                ldm2t(bh[nt], sb + SMV_XH + off);
                ldm2t(bl[nt], sb + SMV_XL + off);
            }
            #pragma unroll
            for (int mt = 0; mt < 3; mt++)
                #pragma unroll
                for (int nt = 0; nt < 4; nt++) {
                    mma16816(d1[mt][nt], ah[mt], bh[nt]);
                    mma16816(d1[mt][nt], ah[mt], bl[nt]);
                    mma16816(d1[mt][nt], al[mt], bh[nt]);
                }
        }
    }
    __syncthreads();

    for (int i = tid; i < 48 * 72 / 2; i += 256) {
        ((uint32_t*)(sm + SMV_WH))[i] = 0u;
        ((uint32_t*)(sm + SMV_WL))[i] = 0u;
    }

    #pragma unroll
    for (int mt = 0; mt < 3; mt++) {
        const int o0 = wm * 48 + mt * 16 + (lane >> 2);
        #pragma unroll
        for (int nt = 0; nt < 4; nt++) {
            const int j0 = wn * 32 + nt * 8 + (lane & 3) * 2;
            const float* dd = d1[mt][nt];
            #pragma unroll
            for (int rr = 0; rr < 2; rr++) {
                const int o = o0 + rr * 8;
                float v0 = dd[rr * 2 + 0] + sBv[o];
                float v1 = dd[rr * 2 + 1] + sBv[o];
                float h0 = __bfloat162float(__float2bfloat16(v0));
                float h1 = __bfloat162float(__float2bfloat16(v1));
                *(uint32_t*)(sm + SMV_XH + (o * 72 + j0) * 2) = bpack2(v0, v1);
                *(uint32_t*)(sm + SMV_XL + (o * 72 + j0) * 2) = bpack2(v0 - h0, v1 - h1);
            }
        }
    }
    __syncthreads();

    for (int i = tid; i < CQ * TV; i += 256) {
        int m = i >> 6, j = i & 63;
        float v = g_Kn[(size_t)(b * CQ + m) * NN + n0 + j];
        uint16_t h, l; bsplit(v, h, l);
        *(uint16_t*)(sm + SMV_WH + (m * 72 + j) * 2) = h;
        *(uint16_t*)(sm + SMV_WL + (m * 72 + j) * 2) = l;
    }
    if (tid < TV)
        *(uint16_t*)(sm + SMV_WH + (32 * 72 + tid) * 2) = 0x3F80;
    __syncthreads();

    float d2[3][3][4];
    #pragma unroll
    for (int mt = 0; mt < 3; mt++)
        #pragma unroll
        for (int nt = 0; nt < 3; nt++)
            #pragma unroll
            for (int e = 0; e < 4; e++) d2[mt][nt][e] = 0.f;

    const int n0w = wid * 24;
    #pragma unroll
    for (int ks = 0; ks < 4; ks++) {
        uint32_t ah[3][4], al[3][4];
        const int acol = ks * 16 + (lane >> 4) * 8;
        #pragma unroll
        for (int mt = 0; mt < 3; mt++) {
            uint32_t off = (uint32_t)(((mt * 16 + ln16) * 72 + acol) * 2);
            ldm4(ah[mt], sb + SMV_WH + off);
            ldm4(al[mt], sb + SMV_WL + off);
        }
        uint32_t bh[3][2], bl[3][2];
        #pragma unroll
        for (int nt = 0; nt < 3; nt++) {
            const int crow = n0w + nt * 8 + (lane & 7);
            const int kcol = ks * 16 + ((lane >> 3) & 1) * 8;
            uint32_t off = (uint32_t)((crow * 72 + kcol) * 2);
            ldm2(bh[nt], sb + SMV_XH + off);
            ldm2(bl[nt], sb + SMV_XL + off);
        }
        #pragma unroll
        for (int mt = 0; mt < 3; mt++)
            #pragma unroll
            for (int nt = 0; nt < 3; nt++) {
                mma16816(d2[mt][nt], ah[mt], bh[nt]);
                mma16816(d2[mt][nt], ah[mt], bl[nt]);
                mma16816(d2[mt][nt], al[mt], bh[nt]);
            }
    }

    float* matp = g_MatPart + (size_t)(b * NTV + tile) * (CQ * CC);
    float* vsp  = g_VsumPart + (size_t)(b * NTV + tile) * CC;
    #pragma unroll
    for (int mt = 0; mt < 3; mt++) {
        const int r0 = mt * 16 + (lane >> 2);
        #pragma unroll
        for (int nt = 0; nt < 3; nt++) {
            const int c0w = n0w + nt * 8 + (lane & 3) * 2;
            const float* dd = d2[mt][nt];
            #pragma unroll
            for (int rr = 0; rr < 2; rr++) {
                const int r = r0 + rr * 8;
                if (r < 32) {
                    matp[r * CC + c0w]     = dd[rr * 2 + 0];
                    matp[r * CC + c0w + 1] = dd[rr * 2 + 1];
                } else if (r == 32) {
                    vsp[c0w]     = dd[rr * 2 + 0];
                    vsp[c0w + 1] = dd[rr * 2 + 1];
                }
            }
        }
    }
}

// ---------------- deterministic reductions ----------------
__global__ __launch_bounds__(256) void ksum_kernel()
{
    const int r = blockIdx.x, b = blockIdx.y;
    const float* p = g_Kn + (size_t)(b * CQ + r) * NN;
    float s = 0.f;
    for (int i = threadIdx.x; i < NN; i += 256) s += p[i];
    __shared__ float red[256];
    red[threadIdx.x] = s;
    __syncthreads();
    for (int st = 128; st > 0; st >>= 1) {
        if (threadIdx.x < st) red[threadIdx.x] += red[threadIdx.x + st];
        __syncthreads();
    }
    if (threadIdx.x == 0) g_KsumE[b * CQ + r] = red[0] + 1e-6f;
}

__global__ __launch_bounds__(256) void matred_kernel()
{
    const int b = blockIdx.y;
    const int i = blockIdx.x * 256 + threadIdx.x;
    const float* p = g_MatPart + (size_t)b * NTV * (CQ * CC) + i;
    float s = 0.f;
    for (int t = 0; t < NTV; t++) s += p[(size_t)t * (CQ * CC)];
    g_Mat[b * CQ * CC + i] = s;
}

__global__ __launch_bounds__(192) void vsumred_kernel()
{
    const int b = blockIdx.x;
    const int c = threadIdx.x;
    const float* p = g_VsumPart + (size_t)b * NTV * CC + c;
    float s = 0.f;
    for (int t = 0; t < NTV; t++) s += p[(size_t)t * CC];
    g_Vsum[b * CC + c] = s;
}

// ---------------- kernel 6: epilogue via mma.sync ----------------
// smem: A = Qn [64 j][40 r] hi/lo; B = Mat [32 r][200 c] hi/lo; stage f32 [192 c][72 j]
#define SF_AH 0
#define SF_AL 5120
#define SF_BH 10240
#define SF_BL 23040
#define SF_ST 35840
#define SF_VS 91136
#define SF_KS 91904
#define SF_TL 92032
#define SF_TOT 92288

__global__ __launch_bounds__(256) void final_mma_kernel(
    const float* __restrict__ gamma, float* __restrict__ out)
{
    extern __shared__ char sm[];
    const uint32_t sb = s2u(sm);
    const int tid = threadIdx.x;
    const int lane = tid & 31;
    const int wid = tid >> 5;
    const int ln16 = lane & 15;
    const int b = blockIdx.y;
    const int n0 = blockIdx.x * TILE;

    // loads
    const float* gq = g_Qn + (size_t)(b * NN + n0) * CQ;
    for (int i = tid; i < TILE * CQ; i += 256) {
        int j = i >> 5, r = i & 31;
        float v = gq[i];
        uint16_t h, l; bsplit(v, h, l);
        *(uint16_t*)(sm + SF_AH + (j * 40 + r) * 2) = h;
        *(uint16_t*)(sm + SF_AL + (j * 40 + r) * 2) = l;
    }
    for (int i = tid; i < CQ * CC; i += 256) {
        int r = i / CC, c = i - r * CC;
        float v = g_Mat[b * CQ * CC + i];
        uint16_t h, l; bsplit(v, h, l);
        *(uint16_t*)(sm + SF_BH + (r * 200 + c) * 2) = h;
        *(uint16_t*)(sm + SF_BL + (r * 200 + c) * 2) = l;
    }
    float* sVS = (float*)(sm + SF_VS);
    float* sKS = (float*)(sm + SF_KS);
    float* sTL = (float*)(sm + SF_TL);
    if (tid < CC) sVS[tid] = g_Vsum[b * CC + tid];
    if (tid < CQ) sKS[tid] = g_KsumE[b * CQ + tid];
    __syncthreads();

    // tail: reconstruct q = hi + lo (error ~2^-17, added to N=16384 -> negligible)
    if (tid < TILE) {
        float s = 0.f;
        #pragma unroll
        for (int r = 0; r < CQ; r++) {
            float q = bf16u(*(uint16_t*)(sm + SF_AH + (tid * 40 + r) * 2))
                    + bf16u(*(uint16_t*)(sm + SF_AL + (tid * 40 + r) * 2));
            s += q * sKS[r];
        }
        sTL[tid] = 1.0f / ((float)NN + s);
    }

    // D[j:64][c:192] = Qn · Mat, K=32; warp grid 2(M=32) x 4(N=48)
    const int wm = wid & 1, wn = wid >> 1;
    float d[2][6][4];
    #pragma unroll
    for (int mt = 0; mt < 2; mt++)
        #pragma unroll
        for (int nt = 0; nt < 6; nt++)
            #pragma unroll
            for (int e = 0; e < 4; e++) d[mt][nt][e] = 0.f;

    #pragma unroll
    for (int ks = 0; ks < 2; ks++) {
        uint32_t ah[2][4], al[2][4];
        const int acol = ks * 16 + (lane >> 4) * 8;
        #pragma unroll
        for (int mt = 0; mt < 2; mt++) {
            uint32_t off = (uint32_t)(((wm * 32 + mt * 16 + ln16) * 40 + acol) * 2);
            ldm4(ah[mt], sb + SF_AH + off);
            ldm4(al[mt], sb + SF_AL + off);
        }
        uint32_t bh[6][2], bl[6][2];
        const int brow = ks * 16 + ln16;
        #pragma unroll
        for (int nt = 0; nt < 6; nt++) {
            uint32_t off = (uint32_t)((brow * 200 + wn * 48 + nt * 8) * 2);
            ldm2t(bh[nt], sb + SF_BH + off);
            ldm2t(bl[nt], sb + SF_BL + off);
        }
        #pragma unroll
        for (int mt = 0; mt < 2; mt++)
            #pragma unroll
            for (int nt = 0; nt < 6; nt++) {
                mma16816(d[mt][nt], ah[mt], bh[nt]);
                mma16816(d[mt][nt], ah[mt], bl[nt]);
                mma16816(d[mt][nt], al[mt], bh[nt]);
            }
    }

    // stage transposed: sST[c][j]
    float* sST = (float*)(sm + SF_ST);   // [192][72]
    #pragma unroll
    for (int mt = 0; mt < 2; mt++) {
        const int j0 = wm * 32 + mt * 16 + (lane >> 2);
        #pragma unroll
        for (int nt = 0; nt < 6; nt++) {
            const int c0 = wn * 48 + nt * 8 + (lane & 3) * 2;
            #pragma unroll
            for (int rr = 0; rr < 2; rr++) {
                const int j = j0 + rr * 8;
                sST[(c0)     * 72 + j] = d[mt][nt][rr * 2 + 0];
                sST[(c0 + 1) * 72 + j] = d[mt][nt][rr * 2 + 1];
            }
        }
    }
    __syncthreads();

    const float g = __ldg(gamma);
    float* ob = out + (size_t)b * CC * NN + n0;
    for (int i = tid; i < CC * TILE; i += 256) {
        int c = i >> 6, j = i & 63;
        ob[(size_t)c * NN + j] = (sVS[c] + sST[c * 72 + j]) * sTL[j] * g;
    }
}

// ---------------- launch ----------------
extern "C" void kernel_launch(void* const* d_in, const int* in_sizes, int n_in,
                              void* d_out, int out_size)
{
    const float* x  = (const float*)d_in[0];
    const float* x1 = (const float*)d_in[1];
    const float* Wq = (const float*)d_in[2];
    const float* bq = (const float*)d_in[3];
    const float* Wk = (const float*)d_in[4];
    const float* bk = (const float*)d_in[5];
    const float* Wv = (const float*)d_in[6];
    const float* bv = (const float*)d_in[7];
    const float* gm = (const float*)d_in[8];
    float* out = (float*)d_out;

    cudaFuncSetAttribute(qk_mma_kernel,    cudaFuncAttributeMaxDynamicSharedMemorySize, SQ_TOT);
    cudaFuncSetAttribute(vmat_mma_kernel,  cudaFuncAttributeMaxDynamicSharedMemorySize, SMV_TOT);
    cudaFuncSetAttribute(final_mma_kernel, cudaFuncAttributeMaxDynamicSharedMemorySize, SF_TOT);

    qk_mma_kernel<<<dim3(NT, BB), 256, SQ_TOT>>>(x1, Wq, bq, Wk, bk);
    vmat_mma_kernel<<<dim3(NTV, BB), 256, SMV_TOT>>>(x, Wv, bv);
    ksum_kernel<<<dim3(CQ, BB), 256>>>();
    matred_kernel<<<dim3((CQ * CC) / 256, BB), 256>>>();
    vsumred_kernel<<<BB, 192>>>();
    final_mma_kernel<<<dim3(NT, BB), 256, SF_TOT>>>(gm, out);
}

// round 8
// speedup vs baseline: 2.9594x; 1.8779x over previous
#include <cuda_runtime.h>
#include <cuda_bf16.h>
#include <cstdint>

#define BB 8
#define CC 192
#define CQ 32
#define NN 16384
#define TILE 64
#define NT (NN / TILE)      // 256 tiles (qk / final)
#define TKX 128
#define NTK (NN / TKX)      // 128 tiles (kx)

// ---------------- scratch (static device globals; no allocations) ----------------
__device__ float g_Qn[(size_t)BB * NN * CQ];            // [b][n][r]
__device__ float g_Kn[(size_t)BB * CQ * NN];            // [b][r][n]
__device__ float g_KXPart[(size_t)BB * NTK * 33 * CC];  // per-tile KX partials (+xsum row)
__device__ float g_KX[BB * 33 * CC];
__device__ float g_Mat[BB * CQ * CC];
__device__ float g_Vsum[BB * CC];
__device__ float g_Ksum[BB * CQ];                       // plain
__device__ float g_KsumE[BB * CQ];                      // + EPS

// ---------------- warp MMA helpers (baseline PTX, sm_80+) ----------------
__device__ __forceinline__ uint32_t s2u(const void* p) {
    uint32_t a;
    asm("{ .reg .u64 t; cvta.to.shared.u64 t, %1; cvt.u32.u64 %0, t; }" : "=r"(a) : "l"(p));
    return a;
}
__device__ __forceinline__ void ldm4(uint32_t* r, uint32_t a) {
    asm volatile("ldmatrix.sync.aligned.m8n8.x4.shared.b16 {%0,%1,%2,%3}, [%4];"
                 : "=r"(r[0]), "=r"(r[1]), "=r"(r[2]), "=r"(r[3]) : "r"(a));
}
__device__ __forceinline__ void ldm2(uint32_t* r, uint32_t a) {
    asm volatile("ldmatrix.sync.aligned.m8n8.x2.shared.b16 {%0,%1}, [%2];"
                 : "=r"(r[0]), "=r"(r[1]) : "r"(a));
}
__device__ __forceinline__ void ldm2t(uint32_t* r, uint32_t a) {
    asm volatile("ldmatrix.sync.aligned.m8n8.x2.trans.shared.b16 {%0,%1}, [%2];"
                 : "=r"(r[0]), "=r"(r[1]) : "r"(a));
}
__device__ __forceinline__ void mma16816(float* d, const uint32_t* a, const uint32_t* b) {
    asm volatile("mma.sync.aligned.m16n8k16.row.col.f32.bf16.bf16.f32 "
                 "{%0,%1,%2,%3},{%4,%5,%6,%7},{%8,%9},{%0,%1,%2,%3};"
                 : "+f"(d[0]), "+f"(d[1]), "+f"(d[2]), "+f"(d[3])
                 : "r"(a[0]), "r"(a[1]), "r"(a[2]), "r"(a[3]), "r"(b[0]), "r"(b[1]));
}
__device__ __forceinline__ uint32_t bpack2(float a, float b) {   // low half = a
    __nv_bfloat162 t = __floats2bfloat162_rn(a, b);
    return *(uint32_t*)&t;
}
__device__ __forceinline__ float bhi(float v) {
    return __bfloat162float(__float2bfloat16(v));
}
__device__ __forceinline__ void bsplit(float v, uint16_t& h, uint16_t& l) {
    __nv_bfloat16 hb = __float2bfloat16(v);
    __nv_bfloat16 lb = __float2bfloat16(v - __bfloat162float(hb));
    h = *(uint16_t*)&hb;
    l = *(uint16_t*)&lb;
}
__device__ __forceinline__ float bf16u(uint16_t u) {
    __nv_bfloat16 t = *(__nv_bfloat16*)&u;
    return __bfloat162float(t);
}
// split a float4 (4 consecutive elems) into two packed-u32 hi and two packed-u32 lo
__device__ __forceinline__ void bsplit4(float4 v, uint32_t* h2, uint32_t* l2) {
    float hx = bhi(v.x), hy = bhi(v.y), hz = bhi(v.z), hw = bhi(v.w);
    h2[0] = bpack2(v.x, v.y);          // rn-rounded hi pair
    h2[1] = bpack2(v.z, v.w);
    l2[0] = bpack2(v.x - hx, v.y - hy);
    l2[1] = bpack2(v.z - hz, v.w - hw);
}

// ---------------- kernel 1: Q,K projection via mma.sync + per-column L2 norm ----------------
#define SQ_XH 0
#define SQ_XL 27648
#define SQ_WH 55296
#define SQ_WL 80896
#define SQ_ST 55296
#define SQ_B  106496
#define SQ_NRM 106752
#define SQ_TOT 107264

__global__ __launch_bounds__(256) void qk_mma_kernel(
    const float* __restrict__ x1, const float* __restrict__ Wq,
    const float* __restrict__ bq, const float* __restrict__ Wk,
    const float* __restrict__ bk)
{
    extern __shared__ char sm[];
    const uint32_t sb = s2u(sm);
    const int tid = threadIdx.x;
    const int lane = tid & 31;
    const int wid = tid >> 5;
    const int ln16 = lane & 15;
    const int b = blockIdx.y;
    const int n0 = blockIdx.x * TILE;

    float* sB = (float*)(sm + SQ_B);
    if (tid < 64) sB[tid] = (tid < CQ) ? bq[tid] : bk[tid - CQ];

    // X: float4 loads, packed u32 stores
    const float* xb = x1 + (size_t)b * CC * NN + n0;
    for (int i = tid; i < CC * 16; i += 256) {
        int c = i >> 4, j4 = (i & 15) * 4;
        float4 v = *(const float4*)(xb + (size_t)c * NN + j4);
        uint32_t h2[2], l2[2];
        bsplit4(v, h2, l2);
        *(uint32_t*)(sm + SQ_XH + (c * 72 + j4) * 2)     = h2[0];
        *(uint32_t*)(sm + SQ_XH + (c * 72 + j4 + 2) * 2) = h2[1];
        *(uint32_t*)(sm + SQ_XL + (c * 72 + j4) * 2)     = l2[0];
        *(uint32_t*)(sm + SQ_XL + (c * 72 + j4 + 2) * 2) = l2[1];
    }
    // W: float4 loads (c contiguous), packed stores
    for (int i = tid; i < 64 * 48; i += 256) {
        int o = i / 48, c4 = (i % 48) * 4;
        float4 v = (o < CQ) ? *(const float4*)(Wq + o * CC + c4)
                            : *(const float4*)(Wk + (o - CQ) * CC + c4);
        uint32_t h2[2], l2[2];
        bsplit4(v, h2, l2);
        *(uint32_t*)(sm + SQ_WH + (o * 200 + c4) * 2)     = h2[0];
        *(uint32_t*)(sm + SQ_WH + (o * 200 + c4 + 2) * 2) = h2[1];
        *(uint32_t*)(sm + SQ_WL + (o * 200 + c4) * 2)     = l2[0];
        *(uint32_t*)(sm + SQ_WL + (o * 200 + c4 + 2) * 2) = l2[1];
    }
    __syncthreads();

    // D[o:64][j:64] = Wqk · X, K=192; warp grid 2(M=32) x 4(N=16)
    const int wm = wid & 1, wn = wid >> 1;
    float d[2][2][4];
    #pragma unroll
    for (int mt = 0; mt < 2; mt++)
        #pragma unroll
        for (int nt = 0; nt < 2; nt++)
            #pragma unroll
            for (int e = 0; e < 4; e++) d[mt][nt][e] = 0.f;

    #pragma unroll
    for (int ks = 0; ks < 12; ks++) {
        uint32_t ah[2][4], al[2][4];
        const int acol = ks * 16 + (lane >> 4) * 8;
        #pragma unroll
        for (int mt = 0; mt < 2; mt++) {
            uint32_t off = (uint32_t)(((wm * 32 + mt * 16 + ln16) * 200 + acol) * 2);
            ldm4(ah[mt], sb + SQ_WH + off);
            ldm4(al[mt], sb + SQ_WL + off);
        }
        uint32_t bh[2][2], bl[2][2];
        const int brow = ks * 16 + ln16;
        #pragma unroll
        for (int nt = 0; nt < 2; nt++) {
            uint32_t off = (uint32_t)((brow * 72 + wn * 16 + nt * 8) * 2);
            ldm2t(bh[nt], sb + SQ_XH + off);
            ldm2t(bl[nt], sb + SQ_XL + off);
        }
        #pragma unroll
        for (int mt = 0; mt < 2; mt++)
            #pragma unroll
            for (int nt = 0; nt < 2; nt++) {
                mma16816(d[mt][nt], ah[mt], bh[nt]);
                mma16816(d[mt][nt], ah[mt], bl[nt]);
                mma16816(d[mt][nt], al[mt], bh[nt]);
            }
    }
    __syncthreads();

    float* sST = (float*)(sm + SQ_ST);   // [64 o][72 j]
    #pragma unroll
    for (int mt = 0; mt < 2; mt++) {
        const int o0 = wm * 32 + mt * 16 + (lane >> 2);
        #pragma unroll
        for (int nt = 0; nt < 2; nt++) {
            const int j0 = wn * 16 + nt * 8 + (lane & 3) * 2;
            #pragma unroll
            for (int rr = 0; rr < 2; rr++) {
                const int o = o0 + rr * 8;
                sST[o * 72 + j0]     = d[mt][nt][rr * 2 + 0] + sB[o];
                sST[o * 72 + j0 + 1] = d[mt][nt][rr * 2 + 1] + sB[o];
            }
        }
    }
    __syncthreads();

    float* sNrm = (float*)(sm + SQ_NRM);
    if (tid < 128) {
        int j = tid & 63, h = tid >> 6;
        float s = 0.f;
        #pragma unroll
        for (int r = 0; r < CQ; r++) {
            float v = sST[(h * CQ + r) * 72 + j];
            s += v * v;
        }
        sNrm[tid] = rsqrtf(s);
    }
    __syncthreads();

    float* gq = g_Qn + (size_t)(b * NN + n0) * CQ;
    for (int i = tid; i < CQ * TILE; i += 256) {
        int j = i >> 5, r = i & 31;
        gq[i] = sST[r * 72 + j] * sNrm[j];
    }
    for (int i = tid; i < CQ * TILE; i += 256) {
        int r = i >> 6, j = i & 63;
        g_Kn[(size_t)(b * CQ + r) * NN + n0 + j] = sST[(CQ + r) * 72 + j] * sNrm[64 + j];
    }
}

// ---------------- kernel 2: KX = Kn_pad · x^T  (48 x 192, K = 128 per CTA) ----------------
#define KX_XH 0            // x chunk hi [192 c][72 j]
#define KX_XL 27648
#define KX_KH 55296        // Kn_pad hi [48 m][72 j]
#define KX_KL 62208
#define KX_TOT 69120

__global__ __launch_bounds__(256) void kx_kernel(const float* __restrict__ x)
{
    extern __shared__ char sm[];
    const uint32_t sb = s2u(sm);
    const int tid = threadIdx.x;
    const int lane = tid & 31;
    const int wid = tid >> 5;
    const int ln16 = lane & 15;
    const int b = blockIdx.y;
    const int tile = blockIdx.x;
    const int n0 = tile * TKX;

    // init Kn_pad rows 32-47: ones row 32, zeros 33-47 (rows 0-31 rewritten per chunk)
    for (int i = tid; i < 16 * 36; i += 256) {      // 16 rows x 72 elems = 36 u32/row... (16*72/2)
        int r = 32 + i / 36, jc = i % 36;
        *(uint32_t*)(sm + KX_KH + (r * 72) * 2 + jc * 4) = (r == 32 && jc < 32) ? 0x3F803F80u : 0u;
        *(uint32_t*)(sm + KX_KL + (r * 72) * 2 + jc * 4) = 0u;
    }

    float d[3][3][4];
    #pragma unroll
    for (int mt = 0; mt < 3; mt++)
        #pragma unroll
        for (int nt = 0; nt < 3; nt++)
            #pragma unroll
            for (int e = 0; e < 4; e++) d[mt][nt][e] = 0.f;

    const int n0w = wid * 24;
    for (int ch = 0; ch < TKX / 64; ch++) {
        __syncthreads();   // prev MMA reads done (and init on ch==0)
        const float* xb = x + (size_t)b * CC * NN + n0 + ch * 64;
        for (int i = tid; i < CC * 16; i += 256) {
            int c = i >> 4, j4 = (i & 15) * 4;
            float4 v = *(const float4*)(xb + (size_t)c * NN + j4);
            uint32_t h2[2], l2[2];
            bsplit4(v, h2, l2);
            *(uint32_t*)(sm + KX_XH + (c * 72 + j4) * 2)     = h2[0];
            *(uint32_t*)(sm + KX_XH + (c * 72 + j4 + 2) * 2) = h2[1];
            *(uint32_t*)(sm + KX_XL + (c * 72 + j4) * 2)     = l2[0];
            *(uint32_t*)(sm + KX_XL + (c * 72 + j4 + 2) * 2) = l2[1];
        }
        const float* kb = g_Kn + (size_t)b * CQ * NN + n0 + ch * 64;
        for (int i = tid; i < CQ * 16; i += 256) {
            int m = i >> 4, j4 = (i & 15) * 4;
            float4 v = *(const float4*)(kb + (size_t)m * NN + j4);
            uint32_t h2[2], l2[2];
            bsplit4(v, h2, l2);
            *(uint32_t*)(sm + KX_KH + (m * 72 + j4) * 2)     = h2[0];
            *(uint32_t*)(sm + KX_KH + (m * 72 + j4 + 2) * 2) = h2[1];
            *(uint32_t*)(sm + KX_KL + (m * 72 + j4) * 2)     = l2[0];
            *(uint32_t*)(sm + KX_KL + (m * 72 + j4 + 2) * 2) = l2[1];
        }
        __syncthreads();

        #pragma unroll
        for (int ks = 0; ks < 4; ks++) {             // K = j, 4 subtiles of 16
            uint32_t ah[3][4], al[3][4];
            const int acol = ks * 16 + (lane >> 4) * 8;
            #pragma unroll
            for (int mt = 0; mt < 3; mt++) {
                uint32_t off = (uint32_t)(((mt * 16 + ln16) * 72 + acol) * 2);
                ldm4(ah[mt], sb + KX_KH + off);
                ldm4(al[mt], sb + KX_KL + off);
            }
            uint32_t bh[3][2], bl[3][2];
            #pragma unroll
            for (int nt = 0; nt < 3; nt++) {
                const int crow = n0w + nt * 8 + (lane & 7);
                const int kcol = ks * 16 + ((lane >> 3) & 1) * 8;
                uint32_t off = (uint32_t)((crow * 72 + kcol) * 2);
                ldm2(bh[nt], sb + KX_XH + off);
                ldm2(bl[nt], sb + KX_XL + off);
            }
            #pragma unroll
            for (int mt = 0; mt < 3; mt++)
                #pragma unroll
                for (int nt = 0; nt < 3; nt++) {
                    mma16816(d[mt][nt], ah[mt], bh[nt]);
                    mma16816(d[mt][nt], ah[mt], bl[nt]);
                    mma16816(d[mt][nt], al[mt], bh[nt]);
                }
        }
    }

    // write partials: rows 0-32 (32 = xsum)
    float* kxp = g_KXPart + (size_t)(b * NTK + tile) * (33 * CC);
    #pragma unroll
    for (int mt = 0; mt < 3; mt++) {
        const int r0 = mt * 16 + (lane >> 2);
        #pragma unroll
        for (int nt = 0; nt < 3; nt++) {
            const int c0 = n0w + nt * 8 + (lane & 3) * 2;
            #pragma unroll
            for (int rr = 0; rr < 2; rr++) {
                const int r = r0 + rr * 8;
                if (r < 33) {
                    kxp[r * CC + c0]     = d[mt][nt][rr * 2 + 0];
                    kxp[r * CC + c0 + 1] = d[mt][nt][rr * 2 + 1];
                }
            }
        }
    }
}

// ---------------- reductions ----------------
__global__ __launch_bounds__(256) void ksum_kernel()
{
    const int r = blockIdx.x, b = blockIdx.y;
    const float* p = g_Kn + (size_t)(b * CQ + r) * NN;
    float s = 0.f;
    for (int i = threadIdx.x; i < NN; i += 256) s += p[i];
    __shared__ float red[256];
    red[threadIdx.x] = s;
    __syncthreads();
    for (int st = 128; st > 0; st >>= 1) {
        if (threadIdx.x < st) red[threadIdx.x] += red[threadIdx.x + st];
        __syncthreads();
    }
    if (threadIdx.x == 0) {
        g_Ksum[b * CQ + r]  = red[0];
        g_KsumE[b * CQ + r] = red[0] + 1e-6f;
    }
}

__global__ __launch_bounds__(256) void kxred_kernel()
{
    const int b = blockIdx.y;
    const int i = blockIdx.x * 256 + threadIdx.x;   // < 33*CC = 6336
    if (i >= 33 * CC) return;
    const float* p = g_KXPart + (size_t)b * NTK * (33 * CC) + i;
    float s = 0.f;
    for (int t = 0; t < NTK; t++) s += p[(size_t)t * (33 * CC)];
    g_KX[b * 33 * CC + i] = s;
}

// ---------------- tiny fp32 contraction: Mat = KX·Wv^T + Ksum·bv^T ; Vsum = Wv·xsum + N·bv ----------------
#define MS_KX 0                      // [33][193] f32
#define MS_W  25476                  // [32][193] f32
#define MS_TOT 50180

__global__ __launch_bounds__(256) void matsmall_kernel(
    const float* __restrict__ Wv, const float* __restrict__ bv)
{
    extern __shared__ char sm[];
    float* sKX = (float*)(sm + MS_KX);
    float* sW  = (float*)(sm + MS_W);
    const int tid = threadIdx.x;
    const int b = blockIdx.y;
    const int c0 = blockIdx.x * 32;

    for (int i = tid; i < 33 * CC; i += 256) {
        int r = i / CC, k = i - r * CC;
        sKX[r * 193 + k] = g_KX[b * 33 * CC + i];
    }
    for (int i = tid; i < 32 * CC; i += 256) {
        int cl = i / CC, k = i - cl * CC;
        sW[cl * 193 + k] = Wv[(c0 + cl) * CC + k];
    }
    __syncthreads();

    const int m = tid >> 3, clb = (tid & 7) * 4;
    float acc[4] = {0.f, 0.f, 0.f, 0.f};
    for (int k = 0; k < CC; k++) {
        float kx = sKX[m * 193 + k];
        #pragma unroll
        for (int q = 0; q < 4; q++) acc[q] += kx * sW[(clb + q) * 193 + k];
    }
    const float ks = g_Ksum[b * CQ + m];
    #pragma unroll
    for (int q = 0; q < 4; q++) {
        int c = c0 + clb + q;
        g_Mat[b * CQ * CC + m * CC + c] = acc[q] + ks * __ldg(&bv[c]);
    }

    if (tid < 32) {
        float vs = 0.f;
        for (int k = 0; k < CC; k++) vs += sW[tid * 193 + k] * sKX[32 * 193 + k];
        int c = c0 + tid;
        g_Vsum[b * CC + c] = vs + (float)NN * __ldg(&bv[c]);
    }
}

// ---------------- kernel 6: epilogue via mma.sync (R7, proven) ----------------
#define SF_AH 0
#define SF_AL 5120
#define SF_BH 10240
#define SF_BL 23040
#define SF_ST 35840
#define SF_VS 91136
#define SF_KS 91904
#define SF_TL 92032
#define SF_TOT 92288

__global__ __launch_bounds__(256) void final_mma_kernel(
    const float* __restrict__ gamma, float* __restrict__ out)
{
    extern __shared__ char sm[];
    const uint32_t sb = s2u(sm);
    const int tid = threadIdx.x;
    const int lane = tid & 31;
    const int wid = tid >> 5;
    const int ln16 = lane & 15;
    const int b = blockIdx.y;
    const int n0 = blockIdx.x * TILE;

    const float* gq = g_Qn + (size_t)(b * NN + n0) * CQ;
    for (int i = tid; i < TILE * CQ; i += 256) {
        int j = i >> 5, r = i & 31;
        float v = gq[i];
        uint16_t h, l; bsplit(v, h, l);
        *(uint16_t*)(sm + SF_AH + (j * 40 + r) * 2) = h;
        *(uint16_t*)(sm + SF_AL + (j * 40 + r) * 2) = l;
    }
    for (int i = tid; i < CQ * CC; i += 256) {
        int r = i / CC, c = i - r * CC;
        float v = g_Mat[b * CQ * CC + i];
        uint16_t h, l; bsplit(v, h, l);
        *(uint16_t*)(sm + SF_BH + (r * 200 + c) * 2) = h;
        *(uint16_t*)(sm + SF_BL + (r * 200 + c) * 2) = l;
    }
    float* sVS = (float*)(sm + SF_VS);
    float* sKS = (float*)(sm + SF_KS);
    float* sTL = (float*)(sm + SF_TL);
    if (tid < CC) sVS[tid] = g_Vsum[b * CC + tid];
    if (tid < CQ) sKS[tid] = g_KsumE[b * CQ + tid];
    __syncthreads();

    if (tid < TILE) {
        float s = 0.f;
        #pragma unroll
        for (int r = 0; r < CQ; r++) {
            float q = bf16u(*(uint16_t*)(sm + SF_AH + (tid * 40 + r) * 2))
                    + bf16u(*(uint16_t*)(sm + SF_AL + (tid * 40 + r) * 2));
            s += q * sKS[r];
        }
        sTL[tid] = 1.0f / ((float)NN + s);
    }

    const int wm = wid & 1, wn = wid >> 1;
    float d[2][6][4];
    #pragma unroll
    for (int mt = 0; mt < 2; mt++)
        #pragma unroll
        for (int nt = 0; nt < 6; nt++)
            #pragma unroll
            for (int e = 0; e < 4; e++) d[mt][nt][e] = 0.f;

    #pragma unroll
    for (int ks = 0; ks < 2; ks++) {
        uint32_t ah[2][4], al[2][4];
        const int acol = ks * 16 + (lane >> 4) * 8;
        #pragma unroll
        for (int mt = 0; mt < 2; mt++) {
            uint32_t off = (uint32_t)(((wm * 32 + mt * 16 + ln16) * 40 + acol) * 2);
            ldm4(ah[mt], sb + SF_AH + off);
            ldm4(al[mt], sb + SF_AL + off);
        }
        uint32_t bh[6][2], bl[6][2];
        const int brow = ks * 16 + ln16;
        #pragma unroll
        for (int nt = 0; nt < 6; nt++) {
            uint32_t off = (uint32_t)((brow * 200 + wn * 48 + nt * 8) * 2);
            ldm2t(bh[nt], sb + SF_BH + off);
            ldm2t(bl[nt], sb + SF_BL + off);
        }
        #pragma unroll
        for (int mt = 0; mt < 2; mt++)
            #pragma unroll
            for (int nt = 0; nt < 6; nt++) {
                mma16816(d[mt][nt], ah[mt], bh[nt]);
                mma16816(d[mt][nt], ah[mt], bl[nt]);
                mma16816(d[mt][nt], al[mt], bh[nt]);
            }
    }

    float* sST = (float*)(sm + SF_ST);   // [192][72]
    #pragma unroll
    for (int mt = 0; mt < 2; mt++) {
        const int j0 = wm * 32 + mt * 16 + (lane >> 2);
        #pragma unroll
        for (int nt = 0; nt < 6; nt++) {
            const int c0 = wn * 48 + nt * 8 + (lane & 3) * 2;
            #pragma unroll
            for (int rr = 0; rr < 2; rr++) {
                const int j = j0 + rr * 8;
                sST[(c0)     * 72 + j] = d[mt][nt][rr * 2 + 0];
                sST[(c0 + 1) * 72 + j] = d[mt][nt][rr * 2 + 1];
            }
        }
    }
    __syncthreads();

    const float g = __ldg(gamma);
    float* ob = out + (size_t)b * CC * NN + n0;
    for (int i = tid; i < CC * TILE; i += 256) {
        int c = i >> 6, j = i & 63;
        ob[(size_t)c * NN + j] = (sVS[c] + sST[c * 72 + j]) * sTL[j] * g;
    }
}

// ---------------- launch ----------------
extern "C" void kernel_launch(void* const* d_in, const int* in_sizes, int n_in,
                              void* d_out, int out_size)
{
    const float* x  = (const float*)d_in[0];
    const float* x1 = (const float*)d_in[1];
    const float* Wq = (const float*)d_in[2];
    const float* bq = (const float*)d_in[3];
    const float* Wk = (const float*)d_in[4];
    const float* bk = (const float*)d_in[5];
    const float* Wv = (const float*)d_in[6];
    const float* bv = (const float*)d_in[7];
    const float* gm = (const float*)d_in[8];
    float* out = (float*)d_out;

    cudaFuncSetAttribute(qk_mma_kernel,    cudaFuncAttributeMaxDynamicSharedMemorySize, SQ_TOT);
    cudaFuncSetAttribute(kx_kernel,        cudaFuncAttributeMaxDynamicSharedMemorySize, KX_TOT);
    cudaFuncSetAttribute(matsmall_kernel,  cudaFuncAttributeMaxDynamicSharedMemorySize, MS_TOT);
    cudaFuncSetAttribute(final_mma_kernel, cudaFuncAttributeMaxDynamicSharedMemorySize, SF_TOT);

    qk_mma_kernel<<<dim3(NT, BB), 256, SQ_TOT>>>(x1, Wq, bq, Wk, bk);
    ksum_kernel<<<dim3(CQ, BB), 256>>>();
    kx_kernel<<<dim3(NTK, BB), 256, KX_TOT>>>(x);
    kxred_kernel<<<dim3((33 * CC + 255) / 256, BB), 256>>>();
    matsmall_kernel<<<dim3(6, BB), 256, MS_TOT>>>(Wv, bv);
    final_mma_kernel<<<dim3(NT, BB), 256, SF_TOT>>>(gm, out);
}